// round 16
// baseline (speedup 1.0000x reference)
#include <cuda_runtime.h>
#include <cuda_bf16.h>
#include <math.h>
#include <stdint.h>

#define S_     2048
#define E_     2048
#define NH     32
#define NG     8
#define DH     64
#define QKV_N  3072   /* (H + 2G) * D */
#define SW_    128
#define ATQ    8      /* queries per attention block */

typedef unsigned long long u64;
struct u64x2 { u64 x, y; };

// ---------------- scratch (__device__ globals; no allocs allowed) ----------
__device__ float g_qkv[(size_t)S_ * QKV_N];
__device__ __nv_bfloat16 g_xhi[(size_t)S_ * E_],     g_xlo[(size_t)S_ * E_];
__device__ __nv_bfloat16 g_wqhi[(size_t)QKV_N * E_], g_wqlo[(size_t)QKV_N * E_];
__device__ __nv_bfloat16 g_wohi[(size_t)E_ * E_],    g_wolo[(size_t)E_ * E_];
__device__ __nv_bfloat16 g_chi[(size_t)S_ * E_],     g_clo[(size_t)S_ * E_];

// ---------------- helpers --------------------------------------------------
__device__ __forceinline__ uint32_t smem_u32(const void* p) {
    return (uint32_t)__cvta_generic_to_shared(p);
}
__device__ __forceinline__ void cp16(uint32_t dst, const void* src) {
    asm volatile("cp.async.cg.shared.global [%0], [%1], 16;"
                 :: "r"(dst), "l"(src) : "memory");
}
__device__ __forceinline__ void ldm_x4(uint32_t* r, uint32_t addr) {
    asm volatile("ldmatrix.sync.aligned.m8n8.x4.shared.b16 {%0,%1,%2,%3}, [%4];"
                 : "=r"(r[0]), "=r"(r[1]), "=r"(r[2]), "=r"(r[3]) : "r"(addr));
}
__device__ __forceinline__ void mma_bf16(float* c, const uint32_t* a,
                                         uint32_t b0, uint32_t b1) {
    asm volatile(
        "mma.sync.aligned.m16n8k16.row.col.f32.bf16.bf16.f32 "
        "{%0,%1,%2,%3},{%4,%5,%6,%7},{%8,%9},{%0,%1,%2,%3};"
        : "+f"(c[0]), "+f"(c[1]), "+f"(c[2]), "+f"(c[3])
        : "r"(a[0]), "r"(a[1]), "r"(a[2]), "r"(a[3]), "r"(b0), "r"(b1));
}
__device__ __forceinline__ void mbar_init(uint32_t addr, uint32_t cnt) {
    asm volatile("mbarrier.init.shared.b64 [%0], %1;" :: "r"(addr), "r"(cnt) : "memory");
}
__device__ __forceinline__ void mbar_arrive(uint32_t addr) {
    asm volatile("mbarrier.arrive.shared.b64 _, [%0];" :: "r"(addr) : "memory");
}
__device__ __forceinline__ void cpasync_arrive(uint32_t addr) {
    asm volatile("cp.async.mbarrier.arrive.noinc.shared.b64 [%0];" :: "r"(addr) : "memory");
}
__device__ __forceinline__ void mbar_wait_parity(uint32_t addr, uint32_t phase) {
    asm volatile(
        "{\n\t.reg .pred P;\n\t"
        "MW_%=:\n\t"
        "mbarrier.try_wait.parity.shared.b64 P, [%0], %1, 0x989680;\n\t"
        "@!P bra MW_%=;\n\t"
        "}" :: "r"(addr), "r"(phase) : "memory");
}
// packed fp32x2 FMA: d = a*b + d (lane-wise on two packed floats)
__device__ __forceinline__ void fma2(u64& d, u64 a, u64 b) {
    asm("fma.rn.f32x2 %0, %1, %2, %0;" : "+l"(d) : "l"(a), "l"(b));
}
__device__ __forceinline__ float hsum2(u64 v) {
    float lo = __uint_as_float((uint32_t)v);
    float hi = __uint_as_float((uint32_t)(v >> 32));
    return lo + hi;
}

// ---------------- fp32 -> (hi, lo) bf16 split, 3 segments fused ------------
__global__ __launch_bounds__(256)
void conv_hilo3(const float* __restrict__ s0, __nv_bfloat16* h0, __nv_bfloat16* l0, int n0,
                const float* __restrict__ s1, __nv_bfloat16* h1, __nv_bfloat16* l1, int n1,
                const float* __restrict__ s2, __nv_bfloat16* h2, __nv_bfloat16* l2, int n2)
{
    int i = blockIdx.x * 256 + threadIdx.x;
    const float* src; __nv_bfloat16* hi; __nv_bfloat16* lo;
    if (i < n0)            { src = s0; hi = h0; lo = l0; }
    else if (i < n0 + n1)  { src = s1; hi = h1; lo = l1; i -= n0; }
    else if (i < n0+n1+n2) { src = s2; hi = h2; lo = l2; i -= n0 + n1; }
    else return;

    float4 v = ((const float4*)src)[i];
    float f[4] = {v.x, v.y, v.z, v.w};
    __nv_bfloat16 h[4], l[4];
    #pragma unroll
    for (int k = 0; k < 4; k++) {
        h[k] = __float2bfloat16(f[k]);
        l[k] = __float2bfloat16(f[k] - __bfloat162float(h[k]));
    }
    __nv_bfloat162* hp = (__nv_bfloat162*)hi;
    __nv_bfloat162* lp = (__nv_bfloat162*)lo;
    hp[2*i]   = __nv_bfloat162(h[0], h[1]);
    hp[2*i+1] = __nv_bfloat162(h[2], h[3]);
    lp[2*i]   = __nv_bfloat162(l[0], l[1]);
    lp[2*i+1] = __nv_bfloat162(l[2], l[3]);
}

// ---------------------------------------------------------------------------
// HMMA split-bf16 GEMM: 128x128 CTA, BK=32, 3-stage mbarrier pipeline,
// hand-interleaved LDSM/MMA stream (R12 arrangement - best measured).
// ---------------------------------------------------------------------------
#define STAGES     3
#define STAGE_B    32768
#define GEMM_SMEM  (STAGES * STAGE_B + 64)

__global__ __launch_bounds__(256, 2)
void gemm_mma(int M, int N, int K,
              const __nv_bfloat16* __restrict__ Ahi,
              const __nv_bfloat16* __restrict__ Alo,
              const __nv_bfloat16* __restrict__ Bhi,
              const __nv_bfloat16* __restrict__ Blo,
              const float* __restrict__ bias,
              float* __restrict__ C)
{
    extern __shared__ char smem[];
    const uint32_t sbase = smem_u32(smem);
    const uint32_t mb    = sbase + STAGES * STAGE_B;
    const int tid  = threadIdx.x;
    const int wid  = tid >> 5, lane = tid & 31;
    const int bm   = blockIdx.y * 128, bn = blockIdx.x * 128;
    const int mi   = (wid >> 2) * 64;
    const int ni   = (wid & 3) * 32;
    const int NC   = K >> 5;

    const __nv_bfloat16* srcp[8];
    uint32_t dsto[8];
    {
        const __nv_bfloat16* srcs[4] = {Ahi, Alo, Bhi, Blo};
        const int r0s[4] = {bm, bm, bn, bn};
        #pragma unroll
        for (int t4 = 0; t4 < 4; t4++)
            #pragma unroll
            for (int rep = 0; rep < 2; rep++) {
                int idx  = tid + rep * 256;
                int r    = idx >> 2, slot = idx & 3;
                srcp[t4 * 2 + rep] = srcs[t4] + (size_t)(r0s[t4] + r) * K + slot * 8;
                dsto[t4 * 2 + rep] = (uint32_t)(t4 * 8192 + r * 64 +
                                     16 * (slot ^ ((r >> 1) & 3)));
            }
    }

    if (tid == 0) {
        #pragma unroll
        for (int s = 0; s < 3; s++) {
            mbar_init(mb + s * 8, 256);
            mbar_init(mb + 24 + s * 8, 8);
        }
    }
    __syncthreads();

    auto fill = [&](int c, int st) {
        uint32_t stb = sbase + st * STAGE_B;
        const int ko = c * 32;
        #pragma unroll
        for (int u = 0; u < 8; u++)
            cp16(stb + dsto[u], srcp[u] + ko);
        cpasync_arrive(mb + st * 8);
    };

    float acc[4][4][4];
    #pragma unroll
    for (int i2 = 0; i2 < 4; i2++)
        #pragma unroll
        for (int j = 0; j < 4; j++)
            #pragma unroll
            for (int q = 0; q < 4; q++) acc[i2][j][q] = 0.f;

    fill(0, 0);
    fill(1, 1);

    uint32_t aoff[2][4], boff[2][2];
    #pragma unroll
    for (int ks = 0; ks < 2; ks++) {
        int slot = ks * 2 + (lane >> 4);
        #pragma unroll
        for (int i2 = 0; i2 < 4; i2++) {
            int r = mi + i2 * 16 + (lane & 15);
            aoff[ks][i2] = (uint32_t)(r * 64 + 16 * (slot ^ ((r >> 1) & 3)));
        }
        #pragma unroll
        for (int jp = 0; jp < 2; jp++) {
            int r = ni + jp * 16 + (lane & 15);
            boff[ks][jp] = (uint32_t)(r * 64 + 16 * (slot ^ ((r >> 1) & 3)));
        }
    }

    int fs = 0; uint32_t fp = 0;
    int es = 0; uint32_t ep = 0;

    for (int c = 0; c < NC; ++c) {
        mbar_wait_parity(mb + fs * 8, fp);
        uint32_t stb = sbase + fs * STAGE_B;

        #pragma unroll
        for (int ks = 0; ks < 2; ks++) {
            uint32_t ah[4][4], al[4][4], bh[2][4], bl[2][4];
            #pragma unroll
            for (int i2 = 0; i2 < 4; i2++)
                ldm_x4(ah[i2], stb + aoff[ks][i2]);
            ldm_x4(bh[0], stb + 16384 + boff[ks][0]);
            ldm_x4(bh[1], stb + 16384 + boff[ks][1]);

            #pragma unroll
            for (int i2 = 0; i2 < 4; i2++) {
                mma_bf16(acc[i2][0], ah[i2], bh[0][0], bh[0][2]);
                mma_bf16(acc[i2][1], ah[i2], bh[0][1], bh[0][3]);
                mma_bf16(acc[i2][2], ah[i2], bh[1][0], bh[1][2]);
                mma_bf16(acc[i2][3], ah[i2], bh[1][1], bh[1][3]);
                ldm_x4(al[i2], stb + 8192 + aoff[ks][i2]);
            }
            ldm_x4(bl[0], stb + 24576 + boff[ks][0]);
            ldm_x4(bl[1], stb + 24576 + boff[ks][1]);

            #pragma unroll
            for (int i2 = 0; i2 < 4; i2++) {
                mma_bf16(acc[i2][0], al[i2], bh[0][0], bh[0][2]);
                mma_bf16(acc[i2][1], al[i2], bh[0][1], bh[0][3]);
                mma_bf16(acc[i2][2], al[i2], bh[1][0], bh[1][2]);
                mma_bf16(acc[i2][3], al[i2], bh[1][1], bh[1][3]);
            }
            #pragma unroll
            for (int i2 = 0; i2 < 4; i2++) {
                mma_bf16(acc[i2][0], ah[i2], bl[0][0], bl[0][2]);
                mma_bf16(acc[i2][1], ah[i2], bl[0][1], bl[0][3]);
                mma_bf16(acc[i2][2], ah[i2], bl[1][0], bl[1][2]);
                mma_bf16(acc[i2][3], ah[i2], bl[1][1], bl[1][3]);
            }
        }

        __syncwarp();
        if (lane == 0) mbar_arrive(mb + 24 + fs * 8);

        const int c2 = c + 2;
        if (c2 < NC) {
            if (c2 >= 3) {
                mbar_wait_parity(mb + 24 + es * 8, ep);
                fill(c2, es);
                if (++es == 3) { es = 0; ep ^= 1; }
            } else {
                fill(c2, 2);
            }
        }
        if (++fs == 3) { fs = 0; fp ^= 1; }
    }

    const int row_l = lane >> 2, colq = (lane & 3) * 2;
    #pragma unroll
    for (int i2 = 0; i2 < 4; i2++) {
        int r0 = bm + mi + i2 * 16 + row_l;
        #pragma unroll
        for (int j = 0; j < 4; j++) {
            int cn = bn + ni + j * 8 + colq;
            float b0 = bias[cn], b1 = bias[cn + 1];
            float* cc = acc[i2][j];
            *(float2*)&C[(size_t)r0 * N + cn]       = make_float2(cc[0] + b0, cc[1] + b1);
            *(float2*)&C[(size_t)(r0 + 8) * N + cn] = make_float2(cc[2] + b0, cc[3] + b1);
        }
    }
}

// ---------------------------------------------------------------------------
// YaRN RoPE: one 256-thread block per position, shared sincos.
// ---------------------------------------------------------------------------
__global__ __launch_bounds__(256)
void rope_kernel(const int* __restrict__ pos_ids)
{
    __shared__ float sc_s[32], sc_c[32];
    const int i   = blockIdx.x;
    const int tid = threadIdx.x;

    if (tid < 32) {
        const int k = tid;
        float freq = __expf(-((float)(2 * k) / 64.0f) * 9.210340371976184f);
        float wl   = 6.283185307179586f / freq;
        float t    = (wl - 128.0f) / (4096.0f - 128.0f);
        t = fminf(fmaxf(t, 0.0f), 1.0f);
        float eff  = freq * (1.0f - t) + (freq * 0.5f) * t;
        float conc = 0.1f * 0.6931471805599453f + 1.0f;
        float ang  = (float)pos_ids[i] * eff * conc;
        sc_s[k] = sinf(ang);
        sc_c[k] = cosf(ang);
    }
    __syncthreads();

    float* row = g_qkv + (size_t)i * QKV_N;
    #pragma unroll
    for (int e = tid; e < (NH + NG) * 32; e += 256) {
        int hh = e >> 5, k = e & 31;
        float* p = row + hh * DH;
        float x1 = p[k], x2 = p[k + 32];
        float sv = sc_s[k], cv = sc_c[k];
        p[k]      = x1 * cv - x2 * sv;
        p[k + 32] = x2 * cv + x1 * sv;
    }
}

// ---------------------------------------------------------------------------
// Windowed sink attention, warp-per-query, 8-query tile per block.
// Score loop uses packed fma.rn.f32x2 (half the FMA issue count).
// ---------------------------------------------------------------------------
#define AKV   136
#define ASTR  68
#define PSTR  576
#define ATT_SMEM_FLOATS (2 * AKV * ASTR + ATQ * 4 * ASTR + ATQ * PSTR)
#define ATT_SMEM_BYTES  (ATT_SMEM_FLOATS * 4)

__global__ __launch_bounds__(256)
void attn_kernel(const float* __restrict__ sinks,
                 __nv_bfloat16* __restrict__ chi,
                 __nv_bfloat16* __restrict__ clo)
{
    extern __shared__ float sm[];
    float* Ks = sm;
    float* Vs = Ks + AKV * ASTR;
    float* Qs = Vs + AKV * ASTR;
    float* ps = Qs + ATQ * 4 * ASTR;

    const int q0  = blockIdx.x * ATQ;
    const int g   = blockIdx.y;
    const int tid = threadIdx.x;
    const int w   = tid >> 5, lane = tid & 31;

    const int j0 = max(0, q0 - (SW_ - 1));
    const int nk = q0 + ATQ - j0;

    const float4* src = (const float4*)g_qkv;
    const int rowq = QKV_N / 4;
    for (int e = tid; e < nk * 16; e += 256) {
        int j = e >> 4, d4 = e & 15;
        ((float4*)(Ks + j * ASTR))[d4] = src[(size_t)(j0 + j) * rowq + (NH + g) * 16 + d4];
        ((float4*)(Vs + j * ASTR))[d4] = src[(size_t)(j0 + j) * rowq + (NH + NG + g) * 16 + d4];
    }
    for (int e = tid; e < ATQ * 4 * 16; e += 256) {
        int q = e >> 6, h = (e >> 4) & 3, d4 = e & 15;
        ((float4*)(Qs + (q * 4 + h) * ASTR))[d4] =
            src[(size_t)(q0 + q) * rowq + (g * 4 + h) * 16 + d4];
    }
    __syncthreads();

    const int i  = q0 + w;
    const int hi = i - j0;
    const int lo = (hi - (SW_ - 1)) > 0 ? (hi - (SW_ - 1)) : 0;

    const u64x2* Q2[4];
    #pragma unroll
    for (int h = 0; h < 4; h++)
        Q2[h] = (const u64x2*)(Qs + (w * 4 + h) * ASTR);

    // f32x2 accumulators: one per (kk, head); both dim-pairs fold in.
    u64 acc2[5][4];
    #pragma unroll
    for (int kk = 0; kk < 5; kk++)
        #pragma unroll
        for (int h = 0; h < 4; h++) acc2[kk][h] = 0ull;

    const u64x2* K2[5];
    #pragma unroll
    for (int kk = 0; kk < 5; kk++)
        K2[kk] = (const u64x2*)(Ks + (kk * 32 + lane) * ASTR);

    #pragma unroll
    for (int d4 = 0; d4 < 16; d4++) {
        u64x2 q0v = Q2[0][d4], q1v = Q2[1][d4], q2v = Q2[2][d4], q3v = Q2[3][d4];
        #pragma unroll
        for (int kk = 0; kk < 5; kk++) {
            u64x2 kv = K2[kk][d4];
            fma2(acc2[kk][0], kv.x, q0v.x); fma2(acc2[kk][0], kv.y, q0v.y);
            fma2(acc2[kk][1], kv.x, q1v.x); fma2(acc2[kk][1], kv.y, q1v.y);
            fma2(acc2[kk][2], kv.x, q2v.x); fma2(acc2[kk][2], kv.y, q2v.y);
            fma2(acc2[kk][3], kv.x, q3v.x); fma2(acc2[kk][3], kv.y, q3v.y);
        }
    }

    float s[5][4];
    #pragma unroll
    for (int kk = 0; kk < 5; kk++) {
        int j = kk * 32 + lane;
        bool valid = (j >= lo) && (j <= hi);
        #pragma unroll
        for (int h = 0; h < 4; h++)
            s[kk][h] = valid ? hsum2(acc2[kk][h]) * 0.125f : -INFINITY;
    }

    // softmax per head; keep normalized probs in s[][]
    float inv[4];
    #pragma unroll
    for (int h = 0; h < 4; h++) {
        const float sink = sinks[g * 4 + h];
        float m = -INFINITY;
        #pragma unroll
        for (int kk = 0; kk < 5; kk++) m = fmaxf(m, s[kk][h]);
        #pragma unroll
        for (int off = 16; off > 0; off >>= 1)
            m = fmaxf(m, __shfl_xor_sync(0xffffffffu, m, off));
        m = fmaxf(m, sink);

        float sum = 0.f;
        #pragma unroll
        for (int kk = 0; kk < 5; kk++) {
            float p = __expf(s[kk][h] - m);
            s[kk][h] = p;
            sum += p;
        }
        #pragma unroll
        for (int off = 16; off > 0; off >>= 1)
            sum += __shfl_xor_sync(0xffffffffu, sum, off);
        inv[h] = 1.f / (sum + __expf(sink - m));
    }

    // one STS.128 per kk: {p0,p1,p2,p3} * inv
    float* prw = ps + w * PSTR;
    #pragma unroll
    for (int kk = 0; kk < 5; kk++) {
        int j = kk * 32 + lane;
        if (j < 144)
            ((float4*)prw)[j] = make_float4(s[kk][0] * inv[0], s[kk][1] * inv[1],
                                            s[kk][2] * inv[2], s[kk][3] * inv[3]);
    }
    __syncwarp();

    // AV: lane owns dims (2*lane, 2*lane+1) -> one LDS.64 per key
    float accA[4], accB[4];
    #pragma unroll
    for (int h = 0; h < 4; h++) { accA[h] = 0.f; accB[h] = 0.f; }
    const float4* pr4 = (const float4*)prw;
    const int d0 = 2 * lane;
    for (int j = lo; j <= hi; j++) {
        float4 pv = pr4[j];
        float2 vv = *(const float2*)(Vs + j * ASTR + d0);
        accA[0] += pv.x * vv.x; accB[0] += pv.x * vv.y;
        accA[1] += pv.y * vv.x; accB[1] += pv.y * vv.y;
        accA[2] += pv.z * vv.x; accB[2] += pv.z * vv.y;
        accA[3] += pv.w * vv.x; accB[3] += pv.w * vv.y;
    }
    #pragma unroll
    for (int h = 0; h < 4; h++) {
        size_t idx = (size_t)i * E_ + (g * 4 + h) * DH + d0;
        float vA = accA[h], vB = accB[h];
        __nv_bfloat16 hA = __float2bfloat16(vA);
        __nv_bfloat16 hB = __float2bfloat16(vB);
        *(__nv_bfloat162*)(chi + idx) = __nv_bfloat162(hA, hB);
        *(__nv_bfloat162*)(clo + idx) = __nv_bfloat162(
            __float2bfloat16(vA - __bfloat162float(hA)),
            __float2bfloat16(vB - __bfloat162float(hB)));
    }
}

// ---------------------------------------------------------------------------
extern "C" void kernel_launch(void* const* d_in, const int* in_sizes, int n_in,
                              void* d_out, int out_size)
{
    const float* x     = (const float*)d_in[0];
    const int*   pos   = (const int*)  d_in[1];
    const float* Wqkv  = (const float*)d_in[3];
    const float* bqkv  = (const float*)d_in[4];
    const float* Wout  = (const float*)d_in[5];
    const float* bout  = (const float*)d_in[6];
    const float* sinks = (const float*)d_in[7];
    float* out = (float*)d_out;

    float* qkv_p = nullptr;
    __nv_bfloat16 *xhi, *xlo, *wqhi, *wqlo, *wohi, *wolo, *chi, *clo;
    cudaGetSymbolAddress((void**)&qkv_p, g_qkv);
    cudaGetSymbolAddress((void**)&xhi,  g_xhi);  cudaGetSymbolAddress((void**)&xlo,  g_xlo);
    cudaGetSymbolAddress((void**)&wqhi, g_wqhi); cudaGetSymbolAddress((void**)&wqlo, g_wqlo);
    cudaGetSymbolAddress((void**)&wohi, g_wohi); cudaGetSymbolAddress((void**)&wolo, g_wolo);
    cudaGetSymbolAddress((void**)&chi,  g_chi);  cudaGetSymbolAddress((void**)&clo,  g_clo);

    cudaFuncSetAttribute(gemm_mma, cudaFuncAttributeMaxDynamicSharedMemorySize, GEMM_SMEM);
    cudaFuncSetAttribute(attn_kernel, cudaFuncAttributeMaxDynamicSharedMemorySize, ATT_SMEM_BYTES);

    // 0) split inputs into bf16 hi/lo (single fused launch)
    {
        const int n0 = (S_ * E_) / 4;
        const int n1 = (QKV_N * E_) / 4;
        const int n2 = (E_ * E_) / 4;
        const int nt = n0 + n1 + n2;
        conv_hilo3<<<(nt + 255) / 256, 256>>>(x, xhi, xlo, n0,
                                              Wqkv, wqhi, wqlo, n1,
                                              Wout, wohi, wolo, n2);
    }

    // 1) qkv = x @ Wqkv^T + bqkv
    gemm_mma<<<dim3(QKV_N / 128, S_ / 128), 256, GEMM_SMEM>>>(
        S_, QKV_N, E_, xhi, xlo, wqhi, wqlo, bqkv, qkv_p);

    // 2) RoPE
    rope_kernel<<<S_, 256>>>(pos);

    // 3) windowed sink attention -> chi/clo directly
    attn_kernel<<<dim3(S_ / ATQ, NG), 256, ATT_SMEM_BYTES>>>(sinks, chi, clo);

    // 4) out = ctx @ Wout^T + bout
    gemm_mma<<<dim3(E_ / 128, S_ / 128), 256, GEMM_SMEM>>>(
        S_, E_, E_, chi, clo, wohi, wolo, bout, out);
}

// round 17
// speedup vs baseline: 1.0164x; 1.0164x over previous
#include <cuda_runtime.h>
#include <cuda_bf16.h>
#include <math.h>
#include <stdint.h>

#define S_     2048
#define E_     2048
#define NH     32
#define NG     8
#define DH     64
#define QKV_N  3072   /* (H + 2G) * D */
#define SW_    128
#define ATQ    16     /* queries per attention block (2 per warp) */

// ---------------- scratch (__device__ globals; no allocs allowed) ----------
__device__ float g_qkv[(size_t)S_ * QKV_N];
__device__ __nv_bfloat16 g_xhi[(size_t)S_ * E_],     g_xlo[(size_t)S_ * E_];
__device__ __nv_bfloat16 g_wqhi[(size_t)QKV_N * E_], g_wqlo[(size_t)QKV_N * E_];
__device__ __nv_bfloat16 g_wohi[(size_t)E_ * E_],    g_wolo[(size_t)E_ * E_];
__device__ __nv_bfloat16 g_chi[(size_t)S_ * E_],     g_clo[(size_t)S_ * E_];

// ---------------- helpers --------------------------------------------------
__device__ __forceinline__ uint32_t smem_u32(const void* p) {
    return (uint32_t)__cvta_generic_to_shared(p);
}
__device__ __forceinline__ void cp16(uint32_t dst, const void* src) {
    asm volatile("cp.async.cg.shared.global [%0], [%1], 16;"
                 :: "r"(dst), "l"(src) : "memory");
}
__device__ __forceinline__ void ldm_x4(uint32_t* r, uint32_t addr) {
    asm volatile("ldmatrix.sync.aligned.m8n8.x4.shared.b16 {%0,%1,%2,%3}, [%4];"
                 : "=r"(r[0]), "=r"(r[1]), "=r"(r[2]), "=r"(r[3]) : "r"(addr));
}
__device__ __forceinline__ void mma_bf16(float* c, const uint32_t* a,
                                         uint32_t b0, uint32_t b1) {
    asm volatile(
        "mma.sync.aligned.m16n8k16.row.col.f32.bf16.bf16.f32 "
        "{%0,%1,%2,%3},{%4,%5,%6,%7},{%8,%9},{%0,%1,%2,%3};"
        : "+f"(c[0]), "+f"(c[1]), "+f"(c[2]), "+f"(c[3])
        : "r"(a[0]), "r"(a[1]), "r"(a[2]), "r"(a[3]), "r"(b0), "r"(b1));
}
__device__ __forceinline__ void mbar_init(uint32_t addr, uint32_t cnt) {
    asm volatile("mbarrier.init.shared.b64 [%0], %1;" :: "r"(addr), "r"(cnt) : "memory");
}
__device__ __forceinline__ void mbar_arrive(uint32_t addr) {
    asm volatile("mbarrier.arrive.shared.b64 _, [%0];" :: "r"(addr) : "memory");
}
__device__ __forceinline__ void cpasync_arrive(uint32_t addr) {
    asm volatile("cp.async.mbarrier.arrive.noinc.shared.b64 [%0];" :: "r"(addr) : "memory");
}
__device__ __forceinline__ void mbar_wait_parity(uint32_t addr, uint32_t phase) {
    asm volatile(
        "{\n\t.reg .pred P;\n\t"
        "MW_%=:\n\t"
        "mbarrier.try_wait.parity.shared.b64 P, [%0], %1, 0x989680;\n\t"
        "@!P bra MW_%=;\n\t"
        "}" :: "r"(addr), "r"(phase) : "memory");
}

// ---------------- fp32 -> (hi, lo) bf16 split, 3 segments fused ------------
__global__ __launch_bounds__(256)
void conv_hilo3(const float* __restrict__ s0, __nv_bfloat16* h0, __nv_bfloat16* l0, int n0,
                const float* __restrict__ s1, __nv_bfloat16* h1, __nv_bfloat16* l1, int n1,
                const float* __restrict__ s2, __nv_bfloat16* h2, __nv_bfloat16* l2, int n2)
{
    int i = blockIdx.x * 256 + threadIdx.x;
    const float* src; __nv_bfloat16* hi; __nv_bfloat16* lo;
    if (i < n0)            { src = s0; hi = h0; lo = l0; }
    else if (i < n0 + n1)  { src = s1; hi = h1; lo = l1; i -= n0; }
    else if (i < n0+n1+n2) { src = s2; hi = h2; lo = l2; i -= n0 + n1; }
    else return;

    float4 v = ((const float4*)src)[i];
    float f[4] = {v.x, v.y, v.z, v.w};
    __nv_bfloat16 h[4], l[4];
    #pragma unroll
    for (int k = 0; k < 4; k++) {
        h[k] = __float2bfloat16(f[k]);
        l[k] = __float2bfloat16(f[k] - __bfloat162float(h[k]));
    }
    __nv_bfloat162* hp = (__nv_bfloat162*)hi;
    __nv_bfloat162* lp = (__nv_bfloat162*)lo;
    hp[2*i]   = __nv_bfloat162(h[0], h[1]);
    hp[2*i+1] = __nv_bfloat162(h[2], h[3]);
    lp[2*i]   = __nv_bfloat162(l[0], l[1]);
    lp[2*i+1] = __nv_bfloat162(l[2], l[3]);
}

// ---------------------------------------------------------------------------
// HMMA split-bf16 GEMM: 128x128 CTA, BK=32, 3-stage mbarrier pipeline,
// hand-interleaved LDSM/MMA stream (R12/R15 arrangement - best measured).
// ---------------------------------------------------------------------------
#define STAGES     3
#define STAGE_B    32768
#define GEMM_SMEM  (STAGES * STAGE_B + 64)

__global__ __launch_bounds__(256, 2)
void gemm_mma(int M, int N, int K,
              const __nv_bfloat16* __restrict__ Ahi,
              const __nv_bfloat16* __restrict__ Alo,
              const __nv_bfloat16* __restrict__ Bhi,
              const __nv_bfloat16* __restrict__ Blo,
              const float* __restrict__ bias,
              float* __restrict__ C)
{
    extern __shared__ char smem[];
    const uint32_t sbase = smem_u32(smem);
    const uint32_t mb    = sbase + STAGES * STAGE_B;
    const int tid  = threadIdx.x;
    const int wid  = tid >> 5, lane = tid & 31;
    const int bm   = blockIdx.y * 128, bn = blockIdx.x * 128;
    const int mi   = (wid >> 2) * 64;
    const int ni   = (wid & 3) * 32;
    const int NC   = K >> 5;

    const __nv_bfloat16* srcp[8];
    uint32_t dsto[8];
    {
        const __nv_bfloat16* srcs[4] = {Ahi, Alo, Bhi, Blo};
        const int r0s[4] = {bm, bm, bn, bn};
        #pragma unroll
        for (int t4 = 0; t4 < 4; t4++)
            #pragma unroll
            for (int rep = 0; rep < 2; rep++) {
                int idx  = tid + rep * 256;
                int r    = idx >> 2, slot = idx & 3;
                srcp[t4 * 2 + rep] = srcs[t4] + (size_t)(r0s[t4] + r) * K + slot * 8;
                dsto[t4 * 2 + rep] = (uint32_t)(t4 * 8192 + r * 64 +
                                     16 * (slot ^ ((r >> 1) & 3)));
            }
    }

    if (tid == 0) {
        #pragma unroll
        for (int s = 0; s < 3; s++) {
            mbar_init(mb + s * 8, 256);
            mbar_init(mb + 24 + s * 8, 8);
        }
    }
    __syncthreads();

    auto fill = [&](int c, int st) {
        uint32_t stb = sbase + st * STAGE_B;
        const int ko = c * 32;
        #pragma unroll
        for (int u = 0; u < 8; u++)
            cp16(stb + dsto[u], srcp[u] + ko);
        cpasync_arrive(mb + st * 8);
    };

    float acc[4][4][4];
    #pragma unroll
    for (int i2 = 0; i2 < 4; i2++)
        #pragma unroll
        for (int j = 0; j < 4; j++)
            #pragma unroll
            for (int q = 0; q < 4; q++) acc[i2][j][q] = 0.f;

    fill(0, 0);
    fill(1, 1);

    uint32_t aoff[2][4], boff[2][2];
    #pragma unroll
    for (int ks = 0; ks < 2; ks++) {
        int slot = ks * 2 + (lane >> 4);
        #pragma unroll
        for (int i2 = 0; i2 < 4; i2++) {
            int r = mi + i2 * 16 + (lane & 15);
            aoff[ks][i2] = (uint32_t)(r * 64 + 16 * (slot ^ ((r >> 1) & 3)));
        }
        #pragma unroll
        for (int jp = 0; jp < 2; jp++) {
            int r = ni + jp * 16 + (lane & 15);
            boff[ks][jp] = (uint32_t)(r * 64 + 16 * (slot ^ ((r >> 1) & 3)));
        }
    }

    int fs = 0; uint32_t fp = 0;
    int es = 0; uint32_t ep = 0;

    for (int c = 0; c < NC; ++c) {
        mbar_wait_parity(mb + fs * 8, fp);
        uint32_t stb = sbase + fs * STAGE_B;

        #pragma unroll
        for (int ks = 0; ks < 2; ks++) {
            uint32_t ah[4][4], al[4][4], bh[2][4], bl[2][4];
            #pragma unroll
            for (int i2 = 0; i2 < 4; i2++)
                ldm_x4(ah[i2], stb + aoff[ks][i2]);
            ldm_x4(bh[0], stb + 16384 + boff[ks][0]);
            ldm_x4(bh[1], stb + 16384 + boff[ks][1]);

            #pragma unroll
            for (int i2 = 0; i2 < 4; i2++) {
                mma_bf16(acc[i2][0], ah[i2], bh[0][0], bh[0][2]);
                mma_bf16(acc[i2][1], ah[i2], bh[0][1], bh[0][3]);
                mma_bf16(acc[i2][2], ah[i2], bh[1][0], bh[1][2]);
                mma_bf16(acc[i2][3], ah[i2], bh[1][1], bh[1][3]);
                ldm_x4(al[i2], stb + 8192 + aoff[ks][i2]);
            }
            ldm_x4(bl[0], stb + 24576 + boff[ks][0]);
            ldm_x4(bl[1], stb + 24576 + boff[ks][1]);

            #pragma unroll
            for (int i2 = 0; i2 < 4; i2++) {
                mma_bf16(acc[i2][0], al[i2], bh[0][0], bh[0][2]);
                mma_bf16(acc[i2][1], al[i2], bh[0][1], bh[0][3]);
                mma_bf16(acc[i2][2], al[i2], bh[1][0], bh[1][2]);
                mma_bf16(acc[i2][3], al[i2], bh[1][1], bh[1][3]);
            }
            #pragma unroll
            for (int i2 = 0; i2 < 4; i2++) {
                mma_bf16(acc[i2][0], ah[i2], bl[0][0], bl[0][2]);
                mma_bf16(acc[i2][1], ah[i2], bl[0][1], bl[0][3]);
                mma_bf16(acc[i2][2], ah[i2], bl[1][0], bl[1][2]);
                mma_bf16(acc[i2][3], ah[i2], bl[1][1], bl[1][3]);
            }
        }

        __syncwarp();
        if (lane == 0) mbar_arrive(mb + 24 + fs * 8);

        const int c2 = c + 2;
        if (c2 < NC) {
            if (c2 >= 3) {
                mbar_wait_parity(mb + 24 + es * 8, ep);
                fill(c2, es);
                if (++es == 3) { es = 0; ep ^= 1; }
            } else {
                fill(c2, 2);
            }
        }
        if (++fs == 3) { fs = 0; fp ^= 1; }
    }

    const int row_l = lane >> 2, colq = (lane & 3) * 2;
    #pragma unroll
    for (int i2 = 0; i2 < 4; i2++) {
        int r0 = bm + mi + i2 * 16 + row_l;
        #pragma unroll
        for (int j = 0; j < 4; j++) {
            int cn = bn + ni + j * 8 + colq;
            float b0 = bias[cn], b1 = bias[cn + 1];
            float* cc = acc[i2][j];
            *(float2*)&C[(size_t)r0 * N + cn]       = make_float2(cc[0] + b0, cc[1] + b1);
            *(float2*)&C[(size_t)(r0 + 8) * N + cn] = make_float2(cc[2] + b0, cc[3] + b1);
        }
    }
}

// ---------------------------------------------------------------------------
// YaRN RoPE: one 256-thread block per position, shared sincos.
// ---------------------------------------------------------------------------
__global__ __launch_bounds__(256)
void rope_kernel(const int* __restrict__ pos_ids)
{
    __shared__ float sc_s[32], sc_c[32];
    const int i   = blockIdx.x;
    const int tid = threadIdx.x;

    if (tid < 32) {
        const int k = tid;
        float freq = __expf(-((float)(2 * k) / 64.0f) * 9.210340371976184f);
        float wl   = 6.283185307179586f / freq;
        float t    = (wl - 128.0f) / (4096.0f - 128.0f);
        t = fminf(fmaxf(t, 0.0f), 1.0f);
        float eff  = freq * (1.0f - t) + (freq * 0.5f) * t;
        float conc = 0.1f * 0.6931471805599453f + 1.0f;
        float ang  = (float)pos_ids[i] * eff * conc;
        sc_s[k] = sinf(ang);
        sc_c[k] = cosf(ang);
    }
    __syncthreads();

    float* row = g_qkv + (size_t)i * QKV_N;
    #pragma unroll
    for (int e = tid; e < (NH + NG) * 32; e += 256) {
        int hh = e >> 5, k = e & 31;
        float* p = row + hh * DH;
        float x1 = p[k], x2 = p[k + 32];
        float sv = sc_s[k], cv = sc_c[k];
        p[k]      = x1 * cv - x2 * sv;
        p[k + 32] = x2 * cv + x1 * sv;
    }
}

// ---------------------------------------------------------------------------
// Windowed sink attention: 16-query tile, warp owns 2 queries x 4 heads.
// One K/V staging amortized over 16 queries; probs overlay the dead K
// region after scores. AV: lane owns dims (2*lane, 2*lane+1).
// ---------------------------------------------------------------------------
#define AKV   144                       /* staged key rows (nk <= 143) */
#define ASTR  68
#define QPSTR 576                       /* per-query prob floats (144 x 4h) */
#define ATT_SMEM_FLOATS (2 * AKV * ASTR + ATQ * 4 * ASTR)
#define ATT_SMEM_BYTES  (ATT_SMEM_FLOATS * 4)

__global__ __launch_bounds__(256)
void attn_kernel(const float* __restrict__ sinks,
                 __nv_bfloat16* __restrict__ chi,
                 __nv_bfloat16* __restrict__ clo)
{
    extern __shared__ float sm[];
    float* Ks = sm;                      // [144][68]; reused for probs later
    float* Vs = Ks + AKV * ASTR;         // [144][68]
    float* Qs = Vs + AKV * ASTR;         // [16][4][68]

    const int q0  = blockIdx.x * ATQ;
    const int g   = blockIdx.y;
    const int tid = threadIdx.x;
    const int w   = tid >> 5, lane = tid & 31;

    const int j0 = max(0, q0 - (SW_ - 1));
    const int nk = q0 + ATQ - j0;        // <= 143

    const float4* src = (const float4*)g_qkv;
    const int rowq = QKV_N / 4;
    for (int e = tid; e < nk * 16; e += 256) {
        int j = e >> 4, d4 = e & 15;
        ((float4*)(Ks + j * ASTR))[d4] = src[(size_t)(j0 + j) * rowq + (NH + g) * 16 + d4];
        ((float4*)(Vs + j * ASTR))[d4] = src[(size_t)(j0 + j) * rowq + (NH + NG + g) * 16 + d4];
    }
    for (int e = tid; e < ATQ * 4 * 16; e += 256) {
        int q = e >> 6, h = (e >> 4) & 3, d4 = e & 15;
        ((float4*)(Qs + (q * 4 + h) * ASTR))[d4] =
            src[(size_t)(q0 + q) * rowq + (g * 4 + h) * 16 + d4];
    }
    __syncthreads();

    // warp w owns queries iq0 = q0+2w, iq1 = iq0+1  (qh index = q*4+h)
    const int lq0 = 2 * w, lq1 = 2 * w + 1;
    const int hi0 = (q0 + lq0) - j0, hi1 = (q0 + lq1) - j0;
    const int lo0 = (hi0 - (SW_ - 1)) > 0 ? (hi0 - (SW_ - 1)) : 0;
    const int lo1 = (hi1 - (SW_ - 1)) > 0 ? (hi1 - (SW_ - 1)) : 0;

    const float4* Qp[8];
    #pragma unroll
    for (int qh = 0; qh < 8; qh++)
        Qp[qh] = (const float4*)(Qs + (lq0 * 4 + qh) * ASTR);  // rows lq0*4 .. lq0*4+7

    float a[5][8];
    #pragma unroll
    for (int kk = 0; kk < 5; kk++)
        #pragma unroll
        for (int qh = 0; qh < 8; qh++) a[kk][qh] = 0.f;

    const float4* Kp[5];
    #pragma unroll
    for (int kk = 0; kk < 5; kk++)
        Kp[kk] = (const float4*)(Ks + (kk * 32 + lane) * ASTR);

    #pragma unroll
    for (int d4 = 0; d4 < 16; d4++) {
        float4 qv[8];
        #pragma unroll
        for (int qh = 0; qh < 8; qh++) qv[qh] = Qp[qh][d4];
        #pragma unroll
        for (int kk = 0; kk < 5; kk++) {
            float4 kv = Kp[kk][d4];
            #pragma unroll
            for (int qh = 0; qh < 8; qh++)
                a[kk][qh] += kv.x * qv[qh].x + kv.y * qv[qh].y +
                             kv.z * qv[qh].z + kv.w * qv[qh].w;
        }
    }

    // mask + scale; softmax per (q,h)
    float inv[8];
    #pragma unroll
    for (int q = 0; q < 2; q++) {
        const int hiq = q ? hi1 : hi0, loq = q ? lo1 : lo0;
        #pragma unroll
        for (int h = 0; h < 4; h++) {
            const int qh = q * 4 + h;
            const float sink = sinks[g * 4 + h];
            float sv[5];
            #pragma unroll
            for (int kk = 0; kk < 5; kk++) {
                int j = kk * 32 + lane;
                bool valid = (j >= loq) && (j <= hiq);
                sv[kk] = valid ? a[kk][qh] * 0.125f : -INFINITY;
            }
            float m = -INFINITY;
            #pragma unroll
            for (int kk = 0; kk < 5; kk++) m = fmaxf(m, sv[kk]);
            #pragma unroll
            for (int off = 16; off > 0; off >>= 1)
                m = fmaxf(m, __shfl_xor_sync(0xffffffffu, m, off));
            m = fmaxf(m, sink);

            float sum = 0.f;
            #pragma unroll
            for (int kk = 0; kk < 5; kk++) {
                float p = __expf(sv[kk] - m);
                a[kk][qh] = p;               // overwrite with prob
                sum += p;
            }
            #pragma unroll
            for (int off = 16; off > 0; off >>= 1)
                sum += __shfl_xor_sync(0xffffffffu, sum, off);
            inv[qh] = 1.f / (sum + __expf(sink - m));
        }
    }

    __syncthreads();   // all K reads done -> safe to overlay probs onto Ks

    // store probs: per query, [key][4 heads] float4 rows in Ks region
    #pragma unroll
    for (int q = 0; q < 2; q++) {
        float* pq = Ks + (lq0 + q) * QPSTR;
        #pragma unroll
        for (int kk = 0; kk < 5; kk++) {
            int j = kk * 32 + lane;
            if (j < AKV)
                ((float4*)pq)[j] = make_float4(
                    a[kk][q*4+0] * inv[q*4+0], a[kk][q*4+1] * inv[q*4+1],
                    a[kk][q*4+2] * inv[q*4+2], a[kk][q*4+3] * inv[q*4+3]);
        }
    }
    __syncwarp();

    // AV per query: lane owns dims (2*lane, 2*lane+1)
    const int d0 = 2 * lane;
    #pragma unroll
    for (int q = 0; q < 2; q++) {
        const int hiq = q ? hi1 : hi0, loq = q ? lo1 : lo0;
        const int iq  = q0 + lq0 + q;
        const float4* pr4 = (const float4*)(Ks + (lq0 + q) * QPSTR);
        float accA[4] = {0.f, 0.f, 0.f, 0.f}, accB[4] = {0.f, 0.f, 0.f, 0.f};
        for (int j = loq; j <= hiq; j++) {
            float4 pv = pr4[j];
            float2 vv = *(const float2*)(Vs + j * ASTR + d0);
            accA[0] += pv.x * vv.x; accB[0] += pv.x * vv.y;
            accA[1] += pv.y * vv.x; accB[1] += pv.y * vv.y;
            accA[2] += pv.z * vv.x; accB[2] += pv.z * vv.y;
            accA[3] += pv.w * vv.x; accB[3] += pv.w * vv.y;
        }
        #pragma unroll
        for (int h = 0; h < 4; h++) {
            size_t idx = (size_t)iq * E_ + (g * 4 + h) * DH + d0;
            float vA = accA[h], vB = accB[h];
            __nv_bfloat16 hA = __float2bfloat16(vA);
            __nv_bfloat16 hB = __float2bfloat16(vB);
            *(__nv_bfloat162*)(chi + idx) = __nv_bfloat162(hA, hB);
            *(__nv_bfloat162*)(clo + idx) = __nv_bfloat162(
                __float2bfloat16(vA - __bfloat162float(hA)),
                __float2bfloat16(vB - __bfloat162float(hB)));
        }
    }
}

// ---------------------------------------------------------------------------
extern "C" void kernel_launch(void* const* d_in, const int* in_sizes, int n_in,
                              void* d_out, int out_size)
{
    const float* x     = (const float*)d_in[0];
    const int*   pos   = (const int*)  d_in[1];
    const float* Wqkv  = (const float*)d_in[3];
    const float* bqkv  = (const float*)d_in[4];
    const float* Wout  = (const float*)d_in[5];
    const float* bout  = (const float*)d_in[6];
    const float* sinks = (const float*)d_in[7];
    float* out = (float*)d_out;

    float* qkv_p = nullptr;
    __nv_bfloat16 *xhi, *xlo, *wqhi, *wqlo, *wohi, *wolo, *chi, *clo;
    cudaGetSymbolAddress((void**)&qkv_p, g_qkv);
    cudaGetSymbolAddress((void**)&xhi,  g_xhi);  cudaGetSymbolAddress((void**)&xlo,  g_xlo);
    cudaGetSymbolAddress((void**)&wqhi, g_wqhi); cudaGetSymbolAddress((void**)&wqlo, g_wqlo);
    cudaGetSymbolAddress((void**)&wohi, g_wohi); cudaGetSymbolAddress((void**)&wolo, g_wolo);
    cudaGetSymbolAddress((void**)&chi,  g_chi);  cudaGetSymbolAddress((void**)&clo,  g_clo);

    cudaFuncSetAttribute(gemm_mma, cudaFuncAttributeMaxDynamicSharedMemorySize, GEMM_SMEM);
    cudaFuncSetAttribute(attn_kernel, cudaFuncAttributeMaxDynamicSharedMemorySize, ATT_SMEM_BYTES);

    // 0) split inputs into bf16 hi/lo (single fused launch)
    {
        const int n0 = (S_ * E_) / 4;
        const int n1 = (QKV_N * E_) / 4;
        const int n2 = (E_ * E_) / 4;
        const int nt = n0 + n1 + n2;
        conv_hilo3<<<(nt + 255) / 256, 256>>>(x, xhi, xlo, n0,
                                              Wqkv, wqhi, wqlo, n1,
                                              Wout, wohi, wolo, n2);
    }

    // 1) qkv = x @ Wqkv^T + bqkv
    gemm_mma<<<dim3(QKV_N / 128, S_ / 128), 256, GEMM_SMEM>>>(
        S_, QKV_N, E_, xhi, xlo, wqhi, wqlo, bqkv, qkv_p);

    // 2) RoPE
    rope_kernel<<<S_, 256>>>(pos);

    // 3) windowed sink attention -> chi/clo directly
    attn_kernel<<<dim3(S_ / ATQ, NG), 256, ATT_SMEM_BYTES>>>(sinks, chi, clo);

    // 4) out = ctx @ Wout^T + bout
    gemm_mma<<<dim3(E_ / 128, S_ / 128), 256, GEMM_SMEM>>>(
        S_, E_, E_, chi, clo, wohi, wolo, bout, out);
}